// round 3
// baseline (speedup 1.0000x reference)
#include <cuda_runtime.h>
#include <cstdint>
#include <cstddef>

// SelfInteraction: N=50000 rows of [s(64) | v(32x3)]
// out_s = c0*(einsum(W000,s,s) + (1/sqrt3)*einsum(W110,v,v))     -> cols 0..63
// out_v = (1/64)*sum_{us,a}(W011[us,a,w]+W101[a,us,w]) s_us v_ai -> cols 64..159
//
// k1: out_s = P @ Wcomb, P = symmetric pair products (u<=v), packed-f32x2 GEMM
// k2: M = s @ Wc (K=64), then out_v[w,i] = sum_a M[a*32+w]*v[a,i], fused

#define N_ROW     160
#define K1PAIRS   2080
#define KTOT      2608
#define KPAD      2624
#define KB        32
#define NCHUNK    (KPAD / KB)      // 82
#define XT_STRIDE 129
#define ST_STRIDE 36
#define MS_STRIDE 132

__device__ __align__(16) float g_wcomb[KPAD * 64];   // 672 KB
__device__ __align__(16) float g_wc[64 * 1024];      // 256 KB
__device__ int g_pU[KPAD];
__device__ int g_pV[KPAD];

__device__ __forceinline__ void fma2(unsigned long long &d,
                                     unsigned long long a,
                                     unsigned long long b) {
    asm("fma.rn.f32x2 %0, %1, %2, %0;" : "+l"(d) : "l"(a), "l"(b));
}
__device__ __forceinline__ unsigned long long dup2(float v) {
    unsigned long long r;
    asm("mov.b64 %0, {%1, %1};" : "=l"(r) : "f"(v));
    return r;
}
__device__ __forceinline__ void upk(unsigned long long v, float &lo, float &hi) {
    asm("mov.b64 {%0, %1}, %2;" : "=f"(lo), "=f"(hi) : "l"(v));
}

// ---------------------------------------------------------------------------
// Init kernels (weight folding; ~1 MB of work per launch, negligible)
// ---------------------------------------------------------------------------
__global__ void build_tables() {
    int t = threadIdx.x;
    if (t < 64) {
        int u = t;
        int off = u * 64 - (u * (u - 1)) / 2;
        for (int v = u; v < 64; v++) { g_pU[off] = u; g_pV[off] = v; off++; }
    } else if (t < 96) {
        int u = t - 64;
        int off = K1PAIRS + u * 32 - (u * (u - 1)) / 2;
        for (int v = u; v < 32; v++) { g_pU[off] = 64 + 3 * u; g_pV[off] = 64 + 3 * v; off++; }
    } else if (t == 96) {
        for (int p = KTOT; p < KPAD; p++) { g_pU[p] = 0; g_pV[p] = 0; }
    }
}

__global__ void build_wcomb(const float* __restrict__ W000,
                            const float* __restrict__ W110) {
    int i = blockIdx.x * 256 + threadIdx.x;
    if (i >= KPAD * 64) return;
    int p = i >> 6, w = i & 63;
    float val = 0.0f;
    const float C0  = 0.013975424859373685f;   // sqrt(1/5120)
    const float IS3 = 0.57735026918962576f;    // 1/sqrt(3)
    if (p < K1PAIRS) {
        int u = g_pU[p], v = g_pV[p];
        float a = W000[(u * 64 + v) * 64 + w];
        if (u != v) a += W000[(v * 64 + u) * 64 + w];
        val = C0 * a;
    } else if (p < KTOT) {
        int u = (g_pU[p] - 64) / 3, v = (g_pV[p] - 64) / 3;
        float a = W110[(u * 32 + v) * 64 + w];
        if (u != v) a += W110[(v * 32 + u) * 64 + w];
        val = (C0 * IS3) * a;
    }
    g_wcomb[i] = val;
}

__global__ void build_wc(const float* __restrict__ W011,
                         const float* __restrict__ W101) {
    int i = blockIdx.x * 256 + threadIdx.x;
    if (i >= 65536) return;
    int us = i >> 10;
    int r  = i & 1023;
    int a  = r >> 5;
    int w  = r & 31;
    // c1 * inv_sqrt3 = sqrt(3/4096)/sqrt(3) = 1/64
    g_wc[i] = 0.015625f * (W011[us * 1024 + a * 32 + w] + W101[a * 2048 + us * 32 + w]);
}

// ---------------------------------------------------------------------------
// k1: out_s — C[128 x 64] = P[128 x KPAD] @ Wcomb[KPAD x 64]
// 128 threads; micro-tile 8 rows x 8 cols, rows packed as f32x2 pairs.
// ---------------------------------------------------------------------------
__global__ void __launch_bounds__(128) k1_outs(const float* __restrict__ x,
                                               float* __restrict__ out, int n) {
    extern __shared__ float sm[];
    float* xt = sm;                          // [160][129] x tile transposed
    float* Ps = xt + N_ROW * XT_STRIDE;      // [KB][128]
    float* Ws = Ps + KB * 128;               // [KB][64]
    const int t  = threadIdx.x;
    const int b0 = blockIdx.x * 128;

    for (int idx = t; idx < 128 * N_ROW; idx += 128) {
        int b = idx / N_ROW;
        int c = idx - b * N_ROW;
        int gb = b0 + b;
        xt[c * XT_STRIDE + b] = (gb < n) ? x[(size_t)gb * N_ROW + c] : 0.0f;
    }

    const int tx = t & 15;   // row group (8 rows)
    const int ty = t >> 4;   // col group (8 cols)

    unsigned long long acc[4][8];
#pragma unroll
    for (int r = 0; r < 4; r++)
#pragma unroll
        for (int c = 0; c < 8; c++) acc[r][c] = 0ull;

    const float4* wg4 = (const float4*)g_wcomb;
    for (int kc = 0; kc < NCHUNK; kc++) {
        __syncthreads();
#pragma unroll
        for (int j = 0; j < 4; j++)
            ((float4*)Ws)[t + j * 128] = wg4[kc * 512 + t + j * 128];
#pragma unroll 4
        for (int e = 0; e < KB; e++) {
            int p = kc * KB + e;
            int cu = g_pU[p], cv = g_pV[p];
            const float* A = xt + cu * XT_STRIDE + t;
            const float* B = xt + cv * XT_STRIDE + t;
            float val;
            if (cu < 64) {
                val = A[0] * B[0];
            } else {
                val = fmaf(A[0], B[0],
                      fmaf(A[XT_STRIDE], B[XT_STRIDE],
                           A[2 * XT_STRIDE] * B[2 * XT_STRIDE]));
            }
            Ps[e * 128 + t] = val;
        }
        __syncthreads();
#pragma unroll 8
        for (int k = 0; k < KB; k++) {
            const ulonglong2 pA = *(const ulonglong2*)(Ps + k * 128 + tx * 8);
            const ulonglong2 pB = *(const ulonglong2*)(Ps + k * 128 + tx * 8 + 4);
            const float4 wA = *(const float4*)(Ws + k * 64 + ty * 8);
            const float4 wB = *(const float4*)(Ws + k * 64 + ty * 8 + 4);
            unsigned long long pr0 = pA.x, pr1 = pA.y, pr2 = pB.x, pr3 = pB.y;
            unsigned long long w0 = dup2(wA.x), w1 = dup2(wA.y),
                               w2 = dup2(wA.z), w3 = dup2(wA.w),
                               w4 = dup2(wB.x), w5 = dup2(wB.y),
                               w6 = dup2(wB.z), w7 = dup2(wB.w);
            fma2(acc[0][0], pr0, w0); fma2(acc[0][1], pr0, w1);
            fma2(acc[0][2], pr0, w2); fma2(acc[0][3], pr0, w3);
            fma2(acc[0][4], pr0, w4); fma2(acc[0][5], pr0, w5);
            fma2(acc[0][6], pr0, w6); fma2(acc[0][7], pr0, w7);
            fma2(acc[1][0], pr1, w0); fma2(acc[1][1], pr1, w1);
            fma2(acc[1][2], pr1, w2); fma2(acc[1][3], pr1, w3);
            fma2(acc[1][4], pr1, w4); fma2(acc[1][5], pr1, w5);
            fma2(acc[1][6], pr1, w6); fma2(acc[1][7], pr1, w7);
            fma2(acc[2][0], pr2, w0); fma2(acc[2][1], pr2, w1);
            fma2(acc[2][2], pr2, w2); fma2(acc[2][3], pr2, w3);
            fma2(acc[2][4], pr2, w4); fma2(acc[2][5], pr2, w5);
            fma2(acc[2][6], pr2, w6); fma2(acc[2][7], pr2, w7);
            fma2(acc[3][0], pr3, w0); fma2(acc[3][1], pr3, w1);
            fma2(acc[3][2], pr3, w2); fma2(acc[3][3], pr3, w3);
            fma2(acc[3][4], pr3, w4); fma2(acc[3][5], pr3, w5);
            fma2(acc[3][6], pr3, w6); fma2(acc[3][7], pr3, w7);
        }
    }

    const int rbase = b0 + tx * 8;
#pragma unroll
    for (int r = 0; r < 4; r++) {
        float lo[8], hi[8];
#pragma unroll
        for (int c = 0; c < 8; c++) upk(acc[r][c], lo[c], hi[c]);
        int rA = rbase + 2 * r;
        if (rA < n) {
            float* o = out + (size_t)rA * N_ROW + ty * 8;
            *(float4*)o       = make_float4(lo[0], lo[1], lo[2], lo[3]);
            *(float4*)(o + 4) = make_float4(lo[4], lo[5], lo[6], lo[7]);
        }
        int rB = rA + 1;
        if (rB < n) {
            float* o = out + (size_t)rB * N_ROW + ty * 8;
            *(float4*)o       = make_float4(hi[0], hi[1], hi[2], hi[3]);
            *(float4*)(o + 4) = make_float4(hi[4], hi[5], hi[6], hi[7]);
        }
    }
}

// ---------------------------------------------------------------------------
// k2: out_v — per 32-row block: M[32x1024] = s @ Wc in 128-col chunks,
// fused epilogue out_v[b,w,i] = sum_a M[b][a*32+w] * v[b,a,i]
// 256 threads.
// ---------------------------------------------------------------------------
__global__ void __launch_bounds__(256) k2_outv(const float* __restrict__ x,
                                               float* __restrict__ out, int n) {
    extern __shared__ float sm[];
    float* st = sm;                          // [64][36]  s transposed
    float* vt = st + 64 * ST_STRIDE;         // [32][96]  v rows
    float* Wb = vt + 32 * 96;                // [64][128] Wc chunk
    float* Ms = Wb + 64 * 128;               // [32][132] M chunk
    const int t  = threadIdx.x;
    const int b0 = blockIdx.x * 32;

    for (int idx = t; idx < 32 * N_ROW; idx += 256) {
        int b = idx / N_ROW;
        int c = idx - b * N_ROW;
        int gb = b0 + b;
        float val = (gb < n) ? x[(size_t)gb * N_ROW + c] : 0.0f;
        if (c < 64) st[c * ST_STRIDE + b] = val;
        else        vt[b * 96 + (c - 64)] = val;
    }

    const int tx = t & 31;   // GEMM col group (4 cols)
    const int ty = t >> 5;   // GEMM row group (4 rows)
    const int be = t >> 3;   // epilogue row 0..31
    const int re = t & 7;    // epilogue output group (12 outputs)

    float acc_out[12];
#pragma unroll
    for (int j = 0; j < 12; j++) acc_out[j] = 0.0f;

    for (int cc = 0; cc < 8; cc++) {
        __syncthreads();
        // stage Wb: rows 0..63, global cols cc*128..+127
#pragma unroll
        for (int j = 0; j < 8; j++) {
            int f  = t + j * 256;      // float4 index 0..2047
            int kk = f >> 5;
            int c4 = f & 31;
            ((float4*)Wb)[kk * 32 + c4] =
                *(const float4*)(g_wc + kk * 1024 + cc * 128 + c4 * 4);
        }
        __syncthreads();

        unsigned long long acc[4][2];
#pragma unroll
        for (int r = 0; r < 4; r++) { acc[r][0] = 0ull; acc[r][1] = 0ull; }
#pragma unroll 8
        for (int k = 0; k < 64; k++) {
            const float4 sv = *(const float4*)(st + k * ST_STRIDE + ty * 4);
            const ulonglong2 wv = *(const ulonglong2*)(Wb + k * 128 + tx * 4);
            unsigned long long s0 = dup2(sv.x), s1 = dup2(sv.y),
                               s2 = dup2(sv.z), s3 = dup2(sv.w);
            fma2(acc[0][0], s0, wv.x); fma2(acc[0][1], s0, wv.y);
            fma2(acc[1][0], s1, wv.x); fma2(acc[1][1], s1, wv.y);
            fma2(acc[2][0], s2, wv.x); fma2(acc[2][1], s2, wv.y);
            fma2(acc[3][0], s3, wv.x); fma2(acc[3][1], s3, wv.y);
        }
#pragma unroll
        for (int r = 0; r < 4; r++) {
            float l0, h0, l1, h1;
            upk(acc[r][0], l0, h0);
            upk(acc[r][1], l1, h1);
            *(float4*)(Ms + (ty * 4 + r) * MS_STRIDE + tx * 4) =
                make_float4(l0, h0, l1, h1);
        }
        __syncthreads();
        // epilogue: thread owns outputs o = re*12 + j, w = o/3, i = o%3
#pragma unroll
        for (int j = 0; j < 12; j++) {
            int w = re * 4 + j / 3;
            int i = j % 3;
#pragma unroll
            for (int la = 0; la < 4; la++) {
                acc_out[j] = fmaf(Ms[be * MS_STRIDE + la * 32 + w],
                                  vt[be * 96 + (cc * 4 + la) * 3 + i],
                                  acc_out[j]);
            }
        }
    }

    int gb = b0 + be;
    if (gb < n) {
        float* o = out + (size_t)gb * N_ROW + 64 + re * 12;
#pragma unroll
        for (int j = 0; j < 12; j++) o[j] = acc_out[j];
    }
}

// ---------------------------------------------------------------------------
extern "C" void kernel_launch(void* const* d_in, const int* in_sizes, int n_in,
                              void* d_out, int out_size) {
    const float* x    = (const float*)d_in[0];
    const float* W000 = (const float*)d_in[1];
    const float* W110 = (const float*)d_in[2];
    const float* W011 = (const float*)d_in[3];
    const float* W101 = (const float*)d_in[4];
    float* out = (float*)d_out;
    int n = in_sizes[0] / N_ROW;

    const int k1_smem = (N_ROW * XT_STRIDE + KB * 128 + KB * 64) * 4;               // 107136
    const int k2_smem = (64 * ST_STRIDE + 32 * 96 + 64 * 128 + 32 * MS_STRIDE) * 4; // 71168
    cudaFuncSetAttribute(k1_outs, cudaFuncAttributeMaxDynamicSharedMemorySize, k1_smem);
    cudaFuncSetAttribute(k2_outv, cudaFuncAttributeMaxDynamicSharedMemorySize, k2_smem);

    build_tables<<<1, 128>>>();
    build_wcomb<<<(KPAD * 64 + 255) / 256, 256>>>(W000, W110);
    build_wc<<<256, 256>>>(W011, W101);
    k1_outs<<<(n + 127) / 128, 128, k1_smem>>>(x, out, n);
    k2_outv<<<(n + 31) / 32, 256, k2_smem>>>(x, out, n);
}

// round 5
// speedup vs baseline: 1.3476x; 1.3476x over previous
#include <cuda_runtime.h>
#include <cstdint>
#include <cstddef>

// SelfInteraction: N=50000 rows of [s(64) | v(32x3)]
// out_s = c0*(einsum(W000,s,s) + (1/sqrt3)*einsum(W110,v,v))     -> cols 0..63
// out_v = (1/64)*sum_{us,a}(W011[us,a,w]+W101[a,us,w]) s_us v_ai -> cols 64..159
//
// k1: out_s = P @ Wcomb, P = symmetric pair products (u<=v), packed-f32x2 GEMM
//     P built on the fly from a pre-transposed xT (global, L2-resident);
//     double-buffered slabs, one __syncthreads per 32-K chunk.
// k2: M = s @ Wc (K=64), then out_v[w,i] = sum_a M[a*32+w]*v[a,i], fused.

#define N_ROW     160
#define K1PAIRS   2080            // s-pairs: 65 chunks of 32 exactly
#define KTOT      2608
#define KPAD      2624            // + v-pairs 528 padded to 544 (17 chunks)
#define KB        32
#define NCHUNK    (KPAD / KB)     // 82
#define SCHUNKS   65              // chunks 0..64 are s-type, 65..81 v-type
#define NPAD      50176
#define ST_STRIDE 36
#define VT_STRIDE 97
#define MS_STRIDE 132

__device__ __align__(16) float g_wcomb[KPAD * 64];   // 672 KB
__device__ __align__(16) float g_wc[64 * 1024];      // 256 KB
__device__ __align__(16) float g_xT[N_ROW * NPAD];   // 32.1 MB transposed x
__device__ int2 g_pUV[KPAD];

__device__ __forceinline__ void fma2(unsigned long long &d,
                                     unsigned long long a,
                                     unsigned long long b) {
    asm("fma.rn.f32x2 %0, %1, %2, %0;" : "+l"(d) : "l"(a), "l"(b));
}
__device__ __forceinline__ unsigned long long dup2(float v) {
    unsigned long long r;
    asm("mov.b64 %0, {%1, %1};" : "=l"(r) : "f"(v));
    return r;
}
__device__ __forceinline__ void upk(unsigned long long v, float &lo, float &hi) {
    asm("mov.b64 {%0, %1}, %2;" : "=f"(lo), "=f"(hi) : "l"(v));
}

// ---------------------------------------------------------------------------
// Init kernels
// ---------------------------------------------------------------------------
__global__ void build_tables() {
    int t = threadIdx.x;
    if (t < 64) {
        int u = t;
        int off = u * 64 - (u * (u - 1)) / 2;
        for (int v = u; v < 64; v++) { g_pUV[off] = make_int2(u, v); off++; }
    } else if (t < 96) {
        int u = t - 64;
        int off = K1PAIRS + u * 32 - (u * (u - 1)) / 2;
        for (int v = u; v < 32; v++) { g_pUV[off] = make_int2(64 + 3 * u, 64 + 3 * v); off++; }
    } else if (t == 96) {
        for (int p = KTOT; p < KPAD; p++) g_pUV[p] = make_int2(64, 64);
    }
}

__global__ void build_wcomb(const float* __restrict__ W000,
                            const float* __restrict__ W110) {
    int i = blockIdx.x * 256 + threadIdx.x;
    if (i >= KPAD * 64) return;
    int p = i >> 6, w = i & 63;
    float val = 0.0f;
    const float C0  = 0.013975424859373685f;   // sqrt(1/5120)
    const float IS3 = 0.57735026918962576f;    // 1/sqrt(3)
    if (p < K1PAIRS) {
        int2 uv = g_pUV[p];
        float a = W000[(uv.x * 64 + uv.y) * 64 + w];
        if (uv.x != uv.y) a += W000[(uv.y * 64 + uv.x) * 64 + w];
        val = C0 * a;
    } else if (p < KTOT) {
        int2 uv = g_pUV[p];
        int u = (uv.x - 64) / 3, v = (uv.y - 64) / 3;
        float a = W110[(u * 32 + v) * 64 + w];
        if (u != v) a += W110[(v * 32 + u) * 64 + w];
        val = (C0 * IS3) * a;
    }
    g_wcomb[i] = val;
}

__global__ void build_wc(const float* __restrict__ W011,
                         const float* __restrict__ W101) {
    int i = blockIdx.x * 256 + threadIdx.x;
    if (i >= 65536) return;
    int us = i >> 10;
    int r  = i & 1023;
    int a  = r >> 5;
    int w  = r & 31;
    // c1 * inv_sqrt3 = sqrt(3/4096)/sqrt(3) = 1/64
    g_wc[i] = 0.015625f * (W011[us * 1024 + a * 32 + w] + W101[a * 2048 + us * 32 + w]);
}

// Transpose x[n][160] -> g_xT[160][NPAD], zero-padded rows >= n.
__global__ void transpose_x(const float* __restrict__ x, int n) {
    __shared__ float tile[32][33];
    int r0 = blockIdx.x * 32, c0 = blockIdx.y * 32;
    int tx = threadIdx.x, ty = threadIdx.y;   // 32 x 8
#pragma unroll
    for (int j = 0; j < 32; j += 8) {
        int r = r0 + ty + j, c = c0 + tx;
        tile[ty + j][tx] = (r < n && c < N_ROW) ? x[(size_t)r * N_ROW + c] : 0.0f;
    }
    __syncthreads();
#pragma unroll
    for (int j = 0; j < 32; j += 8) {
        int c = c0 + ty + j, r = r0 + tx;
        if (c < N_ROW && r < NPAD) g_xT[(size_t)c * NPAD + r] = tile[tx][ty + j];
    }
}

// ---------------------------------------------------------------------------
// k1: out_s — C[128 x 64] = P[128 x KPAD] @ Wcomb[KPAD x 64]
// 128 threads; micro 8 rows x 8 cols, rows packed f32x2.
// Double-buffered Ps/Ws, one sync per chunk. smem = 48 KB -> 4 blocks/SM.
// ---------------------------------------------------------------------------
__device__ __forceinline__ void k1_build(int kc, int buf, int t, int b0,
                                         float* Ps, float* Ws) {
    // stage W slab [KB][64]
    const float4* wg4 = (const float4*)g_wcomb;
    float4* ws4 = (float4*)(Ws + buf * (KB * 64));
#pragma unroll
    for (int j = 0; j < 4; j++)
        ws4[t + j * 128] = wg4[kc * 512 + t + j * 128];
    // build P slab [KB][128]; thread t owns row t of the tile
    float* Pb = Ps + buf * (KB * 128);
    const int2* pt = g_pUV + kc * KB;
    const float* xb = g_xT + b0 + t;
    if (kc < SCHUNKS) {
#pragma unroll 8
        for (int e = 0; e < KB; e++) {
            int2 p = pt[e];
            Pb[e * 128 + t] = xb[p.x * NPAD] * xb[p.y * NPAD];
        }
    } else {
#pragma unroll 4
        for (int e = 0; e < KB; e++) {
            int2 p = pt[e];
            const float* A = xb + p.x * NPAD;
            const float* B = xb + p.y * NPAD;
            Pb[e * 128 + t] = fmaf(A[0], B[0],
                              fmaf(A[NPAD], B[NPAD],
                                   A[2 * NPAD] * B[2 * NPAD]));
        }
    }
}

__global__ void __launch_bounds__(128, 4) k1_outs(float* __restrict__ out, int n) {
    extern __shared__ float sm[];
    float* Ps = sm;                 // [2][KB][128]
    float* Ws = sm + 2 * KB * 128;  // [2][KB][64]
    const int t  = threadIdx.x;
    const int b0 = blockIdx.x * 128;
    const int tx = t & 15;   // row group (8 rows)
    const int ty = t >> 4;   // col group (8 cols)

    unsigned long long acc[4][8];
#pragma unroll
    for (int r = 0; r < 4; r++)
#pragma unroll
        for (int c = 0; c < 8; c++) acc[r][c] = 0ull;

    k1_build(0, 0, t, b0, Ps, Ws);

    for (int kc = 0; kc < NCHUNK; kc++) {
        const int cur = kc & 1;
        __syncthreads();
        const float* Pc = Ps + cur * (KB * 128);
        const float* Wc = Ws + cur * (KB * 64);
#pragma unroll 8
        for (int k = 0; k < KB; k++) {
            const ulonglong2 pA = *(const ulonglong2*)(Pc + k * 128 + tx * 8);
            const ulonglong2 pB = *(const ulonglong2*)(Pc + k * 128 + tx * 8 + 4);
            const float4 wA = *(const float4*)(Wc + k * 64 + ty * 8);
            const float4 wB = *(const float4*)(Wc + k * 64 + ty * 8 + 4);
            unsigned long long pr0 = pA.x, pr1 = pA.y, pr2 = pB.x, pr3 = pB.y;
            unsigned long long w0 = dup2(wA.x), w1 = dup2(wA.y),
                               w2 = dup2(wA.z), w3 = dup2(wA.w),
                               w4 = dup2(wB.x), w5 = dup2(wB.y),
                               w6 = dup2(wB.z), w7 = dup2(wB.w);
            fma2(acc[0][0], pr0, w0); fma2(acc[0][1], pr0, w1);
            fma2(acc[0][2], pr0, w2); fma2(acc[0][3], pr0, w3);
            fma2(acc[0][4], pr0, w4); fma2(acc[0][5], pr0, w5);
            fma2(acc[0][6], pr0, w6); fma2(acc[0][7], pr0, w7);
            fma2(acc[1][0], pr1, w0); fma2(acc[1][1], pr1, w1);
            fma2(acc[1][2], pr1, w2); fma2(acc[1][3], pr1, w3);
            fma2(acc[1][4], pr1, w4); fma2(acc[1][5], pr1, w5);
            fma2(acc[1][6], pr1, w6); fma2(acc[1][7], pr1, w7);
            fma2(acc[2][0], pr2, w0); fma2(acc[2][1], pr2, w1);
            fma2(acc[2][2], pr2, w2); fma2(acc[2][3], pr2, w3);
            fma2(acc[2][4], pr2, w4); fma2(acc[2][5], pr2, w5);
            fma2(acc[2][6], pr2, w6); fma2(acc[2][7], pr2, w7);
            fma2(acc[3][0], pr3, w0); fma2(acc[3][1], pr3, w1);
            fma2(acc[3][2], pr3, w2); fma2(acc[3][3], pr3, w3);
            fma2(acc[3][4], pr3, w4); fma2(acc[3][5], pr3, w5);
            fma2(acc[3][6], pr3, w6); fma2(acc[3][7], pr3, w7);
        }
        if (kc + 1 < NCHUNK)
            k1_build(kc + 1, cur ^ 1, t, b0, Ps, Ws);
    }

    const int rbase = b0 + tx * 8;
#pragma unroll
    for (int r = 0; r < 4; r++) {
        float lo[8], hi[8];
#pragma unroll
        for (int c = 0; c < 8; c++) upk(acc[r][c], lo[c], hi[c]);
        int rA = rbase + 2 * r;
        if (rA < n) {
            float* o = out + (size_t)rA * N_ROW + ty * 8;
            *(float4*)o       = make_float4(lo[0], lo[1], lo[2], lo[3]);
            *(float4*)(o + 4) = make_float4(lo[4], lo[5], lo[6], lo[7]);
        }
        int rB = rA + 1;
        if (rB < n) {
            float* o = out + (size_t)rB * N_ROW + ty * 8;
            *(float4*)o       = make_float4(hi[0], hi[1], hi[2], hi[3]);
            *(float4*)(o + 4) = make_float4(hi[4], hi[5], hi[6], hi[7]);
        }
    }
}

// ---------------------------------------------------------------------------
// k2: out_v — per 32-row block: M[32x1024] = s @ Wc in 128-col chunks,
// fused epilogue out_v[b,w,i] = sum_a M[b][a*32+w] * v[b,a,i].
// 256 threads; Wb double-buffered; vt padded to kill 4-way conflicts.
// ---------------------------------------------------------------------------
__global__ void __launch_bounds__(256) k2_outv(const float* __restrict__ x,
                                               float* __restrict__ out, int n) {
    extern __shared__ float sm[];
    float* st = sm;                          // [64][36]  s transposed
    float* vt = st + 64 * ST_STRIDE;         // [32][97]  v rows (padded)
    float* Wb = vt + 32 * VT_STRIDE;         // [2][64][128] Wc chunk
    float* Ms = Wb + 2 * 64 * 128;           // [32][132] M chunk
    const int t  = threadIdx.x;
    const int b0 = blockIdx.x * 32;

    for (int idx = t; idx < 32 * N_ROW; idx += 256) {
        int b = idx / N_ROW;
        int c = idx - b * N_ROW;
        int gb = b0 + b;
        float val = (gb < n) ? x[(size_t)gb * N_ROW + c] : 0.0f;
        if (c < 64) st[c * ST_STRIDE + b] = val;
        else        vt[b * VT_STRIDE + (c - 64)] = val;
    }

    const int tx = t & 31;   // GEMM col group (4 cols)
    const int ty = t >> 5;   // GEMM row group (4 rows)
    const int be = t >> 3;   // epilogue row 0..31
    const int re = t & 7;    // epilogue output group (12 outputs)

    // prologue: stage Wb buf0 (chunk 0)
#pragma unroll
    for (int j = 0; j < 8; j++) {
        int f  = t + j * 256;
        int kk = f >> 5;
        int c4 = f & 31;
        ((float4*)Wb)[kk * 32 + c4] = *(const float4*)(g_wc + kk * 1024 + c4 * 4);
    }

    float acc_out[12];
#pragma unroll
    for (int j = 0; j < 12; j++) acc_out[j] = 0.0f;

    for (int cc = 0; cc < 8; cc++) {
        const int cur = cc & 1;
        __syncthreads();   // staging of cur done; prev epilogue done with Ms
        const float* Wc = Wb + cur * (64 * 128);

        unsigned long long acc[4][2];
#pragma unroll
        for (int r = 0; r < 4; r++) { acc[r][0] = 0ull; acc[r][1] = 0ull; }
#pragma unroll 8
        for (int k = 0; k < 64; k++) {
            const float4 sv = *(const float4*)(st + k * ST_STRIDE + ty * 4);
            const ulonglong2 wv = *(const ulonglong2*)(Wc + k * 128 + tx * 4);
            unsigned long long s0 = dup2(sv.x), s1 = dup2(sv.y),
                               s2 = dup2(sv.z), s3 = dup2(sv.w);
            fma2(acc[0][0], s0, wv.x); fma2(acc[0][1], s0, wv.y);
            fma2(acc[1][0], s1, wv.x); fma2(acc[1][1], s1, wv.y);
            fma2(acc[2][0], s2, wv.x); fma2(acc[2][1], s2, wv.y);
            fma2(acc[3][0], s3, wv.x); fma2(acc[3][1], s3, wv.y);
        }

        // stage next chunk into the other buffer (overlaps with Ms/epilogue)
        if (cc + 1 < 8) {
            float4* wd = (float4*)(Wb + (cur ^ 1) * (64 * 128));
#pragma unroll
            for (int j = 0; j < 8; j++) {
                int f  = t + j * 256;
                int kk = f >> 5;
                int c4 = f & 31;
                wd[kk * 32 + c4] =
                    *(const float4*)(g_wc + kk * 1024 + (cc + 1) * 128 + c4 * 4);
            }
        }

#pragma unroll
        for (int r = 0; r < 4; r++) {
            float l0, h0, l1, h1;
            upk(acc[r][0], l0, h0);
            upk(acc[r][1], l1, h1);
            *(float4*)(Ms + (ty * 4 + r) * MS_STRIDE + tx * 4) =
                make_float4(l0, h0, l1, h1);
        }
        __syncthreads();
        // epilogue: thread owns outputs o = re*12 + j, w = re*4 + j/3, i = j%3
#pragma unroll
        for (int j = 0; j < 12; j++) {
            int w = re * 4 + j / 3;
            int i = j % 3;
#pragma unroll
            for (int la = 0; la < 4; la++) {
                acc_out[j] = fmaf(Ms[be * MS_STRIDE + la * 32 + w],
                                  vt[be * VT_STRIDE + (cc * 4 + la) * 3 + i],
                                  acc_out[j]);
            }
        }
    }

    int gb = b0 + be;
    if (gb < n) {
        float* o = out + (size_t)gb * N_ROW + 64 + re * 12;
#pragma unroll
        for (int j = 0; j < 12; j++) o[j] = acc_out[j];
    }
}

// ---------------------------------------------------------------------------
extern "C" void kernel_launch(void* const* d_in, const int* in_sizes, int n_in,
                              void* d_out, int out_size) {
    const float* x    = (const float*)d_in[0];
    const float* W000 = (const float*)d_in[1];
    const float* W110 = (const float*)d_in[2];
    const float* W011 = (const float*)d_in[3];
    const float* W101 = (const float*)d_in[4];
    float* out = (float*)d_out;
    int n = in_sizes[0] / N_ROW;

    const int k1_smem = (2 * KB * 128 + 2 * KB * 64) * 4;   // 49152
    const int k2_smem = (64 * ST_STRIDE + 32 * VT_STRIDE +
                         2 * 64 * 128 + 32 * MS_STRIDE) * 4; // 104064
    cudaFuncSetAttribute(k1_outs, cudaFuncAttributeMaxDynamicSharedMemorySize, k1_smem);
    cudaFuncSetAttribute(k2_outv, cudaFuncAttributeMaxDynamicSharedMemorySize, k2_smem);

    build_tables<<<1, 128>>>();
    build_wcomb<<<(KPAD * 64 + 255) / 256, 256>>>(W000, W110);
    build_wc<<<256, 256>>>(W011, W101);
    transpose_x<<<dim3((NPAD + 31) / 32, 5), dim3(32, 8)>>>(x, n);
    k1_outs<<<(n + 127) / 128, 128, k1_smem>>>(out, n);
    k2_outv<<<(n + 31) / 32, 256, k2_smem>>>(x, out, n);
}